// round 15
// baseline (speedup 1.0000x reference)
#include <cuda_runtime.h>
#include <cuda_fp16.h>
#include <math.h>
#include <stdint.h>

#define Bsz  4
#define Nseq 2048
#define Cdim 64
#define Hn   16
#define Dh   64
#define HID  1024
#define MTOT (Bsz*Nseq)     // 8192
#define QSC 0.18033688011112042f            /* 0.125 * log2(e) */

// Scratch (device globals)
__device__ __half g_qh[(size_t)Bsz*Hn*Nseq*Dh];   // [bh][n][d], pre-scaled
__device__ __half g_kh[(size_t)Bsz*Hn*Nseq*Dh];   // [bh][n][d]
__device__ __half g_vt[(size_t)Bsz*Hn*Dh*Nseq];   // [bh][d][n]  (V transposed)
__device__ __half g_ctxh[(size_t)MTOT*HID];       // [n][1024] half
__device__ __half g_woh[(size_t)Cdim*HID];        // [n=64][k=1024] (Wo^T, half)
__device__ __half g_wqh[(size_t)(3*HID)*Cdim];    // [n=3072][k=64] (Wq^T, half)

__device__ __forceinline__ float ex2f(float x) {
    float r; asm("ex2.approx.ftz.f32 %0, %1;" : "=f"(r) : "f"(x)); return r;
}
__device__ __forceinline__ uint32_t ex2h2(uint32_t x) {
    uint32_t r; asm("ex2.approx.f16x2 %0, %1;" : "=r"(r) : "r"(x)); return r;
}
__device__ __forceinline__ uint32_t h2u(__half2 h) { return *(uint32_t*)&h; }
__device__ __forceinline__ __half2 u2h(uint32_t u) { return *(__half2*)&u; }

// fp32-accumulator mma (projection kernels)
__device__ __forceinline__ void mma_f16(float d[4], const uint32_t a[4],
                                        uint32_t b0, uint32_t b1) {
    asm volatile("mma.sync.aligned.m16n8k16.row.col.f32.f16.f16.f32 "
        "{%0,%1,%2,%3}, {%4,%5,%6,%7}, {%8,%9}, {%0,%1,%2,%3};"
        : "+f"(d[0]), "+f"(d[1]), "+f"(d[2]), "+f"(d[3])
        : "r"(a[0]), "r"(a[1]), "r"(a[2]), "r"(a[3]), "r"(b0), "r"(b1));
}
// fp16-accumulator mma (attention)
__device__ __forceinline__ void mma_h16(uint32_t d[2],
                                        uint32_t a0, uint32_t a1, uint32_t a2, uint32_t a3,
                                        uint32_t b0, uint32_t b1) {
    asm volatile("mma.sync.aligned.m16n8k16.row.col.f16.f16.f16.f16 "
        "{%0,%1}, {%2,%3,%4,%5}, {%6,%7}, {%0,%1};"
        : "+r"(d[0]), "+r"(d[1])
        : "r"(a0), "r"(a1), "r"(a2), "r"(a3), "r"(b0), "r"(b1));
}
// ldmatrix x4: four 8x8 b16 matrices -> 4 fragment regs
__device__ __forceinline__ void ldsm4(uint32_t r[4], uint32_t addr) {
    asm volatile("ldmatrix.sync.aligned.m8n8.x4.shared.b16 {%0,%1,%2,%3}, [%4];"
        : "=r"(r[0]), "=r"(r[1]), "=r"(r[2]), "=r"(r[3]) : "r"(addr));
}
__device__ __forceinline__ void cp16(uint32_t dst, const void* src) {
    asm volatile("cp.async.cg.shared.global [%0], [%1], 16;" :: "r"(dst), "l"(src));
}
__device__ __forceinline__ void cp_commit() {
    asm volatile("cp.async.commit_group;");
}
__device__ __forceinline__ void cp_wait0() {
    asm volatile("cp.async.wait_group 0;" ::: "memory");
}
__device__ __forceinline__ void cp_wait1() {
    asm volatile("cp.async.wait_group 1;" ::: "memory");
}

// ===========================================================================
// Kernel 0: merged weight conversion (unchanged).
// ===========================================================================
__global__ __launch_bounds__(256) void wconv_all_kernel(
    const float* __restrict__ Wq, const float* __restrict__ Wo)
{
    const int tid = threadIdx.x;
    if (blockIdx.x < 48) {
        __shared__ float T[64][65];
        const int j0 = blockIdx.x * 64;
        #pragma unroll
        for (int it = 0; it < 16; it++) {
            int idx = tid + it*256;
            int k = idx >> 6, n = idx & 63;
            T[k][n] = Wq[(size_t)k*(3*HID) + j0 + n];
        }
        __syncthreads();
        #pragma unroll
        for (int it = 0; it < 2; it++) {
            int idx = tid + it*256;
            int n = idx >> 3, kb = (idx & 7) * 8;
            uint4 o;
            o.x = h2u(__floats2half2_rn(T[kb+0][n], T[kb+1][n]));
            o.y = h2u(__floats2half2_rn(T[kb+2][n], T[kb+3][n]));
            o.z = h2u(__floats2half2_rn(T[kb+4][n], T[kb+5][n]));
            o.w = h2u(__floats2half2_rn(T[kb+6][n], T[kb+7][n]));
            *(uint4*)&g_wqh[(size_t)(j0 + n)*Cdim + kb] = o;
        }
    } else {
        int base = (blockIdx.x - 48) * 1024 + tid * 4;
        int n = base >> 10, k = base & 1023;
        #pragma unroll
        for (int j = 0; j < 4; j++)
            g_woh[base + j] = __float2half_rn(Wo[(size_t)(k + j)*Cdim + n]);
    }
}

// ===========================================================================
// Kernel 1: QKV projection via fp16 mma (unchanged).
// ===========================================================================
#define XPAD 72
#define VTP 136
__global__ __launch_bounds__(256) void qkv_kernel(
    const float* __restrict__ X, const float* __restrict__ bias)
{
    __shared__ __half Xh[128*XPAD];
    __shared__ __half Wh[64*XPAD];
    __shared__ __half VTs[64*VTP];
    const int m0 = blockIdx.y * 128;
    const int jbase = blockIdx.x * 256;
    const int tid = threadIdx.x;
    const int w = tid >> 5, lane = tid & 31;
    const int q = lane & 3, g = lane >> 2;

    #pragma unroll
    for (int it = 0; it < 8; it++) {
        int idx = tid + it*256;
        int r = idx >> 4, c = (idx & 15) * 4;
        float4 v = ((const float4*)(X + (size_t)m0*Cdim))[idx];
        uint2 p;
        p.x = h2u(__floats2half2_rn(v.x, v.y));
        p.y = h2u(__floats2half2_rn(v.z, v.w));
        *(uint2*)&Xh[r*XPAD + c] = p;
    }
    __syncthreads();

    const int rA = 16*w + g;
    uint32_t a[4][4];
    #pragma unroll
    for (int ks = 0; ks < 4; ks++) {
        a[ks][0] = *(uint32_t*)&Xh[rA*XPAD + 16*ks + 2*q];
        a[ks][1] = *(uint32_t*)&Xh[(rA+8)*XPAD + 16*ks + 2*q];
        a[ks][2] = *(uint32_t*)&Xh[rA*XPAD + 16*ks + 8 + 2*q];
        a[ks][3] = *(uint32_t*)&Xh[(rA+8)*XPAD + 16*ks + 8 + 2*q];
    }

    const int three = jbase / HID;
    const int bb = m0 >> 11, n0 = m0 & 2047;
    const int nA = n0 + rA, nB = n0 + rA + 8;

    for (int js = 0; js < 4; js++) {
        const int j0 = jbase + js*64;
        const int h  = (j0 >> 6) & 15;

        #pragma unroll
        for (int it = 0; it < 2; it++) {
            int idx = tid + it*256;
            int n = idx >> 3, kb = (idx & 7) * 8;
            *(uint4*)&Wh[n*XPAD + kb] =
                *(const uint4*)&g_wqh[(size_t)(j0 + n)*Cdim + kb];
        }
        __syncthreads();

        #pragma unroll
        for (int nc = 0; nc < 8; nc++) {
            float d[4] = {0.f, 0.f, 0.f, 0.f};
            #pragma unroll
            for (int ks = 0; ks < 4; ks++) {
                uint32_t b0 = *(uint32_t*)&Wh[(8*nc + g)*XPAD + 16*ks + 2*q];
                uint32_t b1 = *(uint32_t*)&Wh[(8*nc + g)*XPAD + 16*ks + 8 + 2*q];
                mma_f16(d, a[ks], b0, b1);
            }
            const int col = 8*nc + 2*q;
            float bx = bias[j0 + col], by = bias[j0 + col + 1];
            float v0 = d[0] + bx, v1 = d[1] + by;
            float v2 = d[2] + bx, v3 = d[3] + by;
            if (three == 0) {
                v0 *= QSC; v1 *= QSC; v2 *= QSC; v3 *= QSC;
                *(uint32_t*)&g_qh[((size_t)(bb*Hn + h)*Nseq + nA)*Dh + col] =
                    h2u(__floats2half2_rn(v0, v1));
                *(uint32_t*)&g_qh[((size_t)(bb*Hn + h)*Nseq + nB)*Dh + col] =
                    h2u(__floats2half2_rn(v2, v3));
            } else if (three == 1) {
                *(uint32_t*)&g_kh[((size_t)(bb*Hn + h)*Nseq + nA)*Dh + col] =
                    h2u(__floats2half2_rn(v0, v1));
                *(uint32_t*)&g_kh[((size_t)(bb*Hn + h)*Nseq + nB)*Dh + col] =
                    h2u(__floats2half2_rn(v2, v3));
            } else {
                VTs[(col    )*VTP + rA]     = __float2half_rn(v0);
                VTs[(col + 1)*VTP + rA]     = __float2half_rn(v1);
                VTs[(col    )*VTP + rA + 8] = __float2half_rn(v2);
                VTs[(col + 1)*VTP + rA + 8] = __float2half_rn(v3);
            }
        }

        if (three == 2) {
            __syncthreads();
            size_t base = (size_t)(bb*Hn + h)*Dh;
            #pragma unroll
            for (int it = 0; it < 4; it++) {
                int idx = tid + it*256;
                int d = idx >> 4, c = (idx & 15) * 8;
                *(uint4*)&g_vt[(base + d)*Nseq + n0 + c] = *(uint4*)&VTs[d*VTP + c];
            }
        }
        __syncthreads();
    }
}

// ===========================================================================
// Kernel 2: fp16 flash attention (unchanged — at the legacy mma.sync floor).
// ===========================================================================
#define KPADH 72
#define VPADH 136
#define KS_HALVES (128*KPADH)                 // 9216
#define VT_HALVES (64*VPADH)                  // 8704
#define BUF_HALVES (KS_HALVES + VT_HALVES)    // 17920
#define SM_ATTN_BYTES (2*BUF_HALVES*2)        // 71680 B

__global__ __launch_bounds__(128) void attn_kernel()
{
    extern __shared__ __half smh[];
    const uint32_t smbase = (uint32_t)__cvta_generic_to_shared(smh);

    const int tid = threadIdx.x;
    const int w = tid >> 5, lane = tid & 31;
    const int q = lane & 3, gg = lane >> 2;
    const int lrow = lane & 7, lhi = lane >> 3;
    const int bh = blockIdx.y;
    const int q0 = blockIdx.x * 64;

    const __half* Kg  = g_kh + (size_t)bh*Nseq*Dh;
    const __half* Vtg = g_vt + (size_t)bh*Dh*Nseq;

    {
        const __half* Qg = g_qh + ((size_t)bh*Nseq + q0)*Dh;
        #pragma unroll
        for (int it = 0; it < 4; it++) {
            int idx = tid + it*128;
            int r = idx >> 3, c = (idx & 7) * 8;
            *(uint4*)&smh[r*KPADH + c] = ((const uint4*)Qg)[idx];
        }
    }
    __syncthreads();
    const int rA = 16*w + gg;
    uint32_t qa[4][4];
    #pragma unroll
    for (int ks = 0; ks < 4; ks++) {
        qa[ks][0] = *(uint32_t*)&smh[rA*KPADH + 16*ks + 2*q];
        qa[ks][1] = *(uint32_t*)&smh[(rA+8)*KPADH + 16*ks + 2*q];
        qa[ks][2] = *(uint32_t*)&smh[rA*KPADH + 16*ks + 8 + 2*q];
        qa[ks][3] = *(uint32_t*)&smh[(rA+8)*KPADH + 16*ks + 8 + 2*q];
    }
    __syncthreads();

    {
        uint32_t ksb = smbase;
        uint32_t vtb = smbase + KS_HALVES*2;
        #pragma unroll
        for (int it = 0; it < 8; it++) {
            int idx = tid + it*128;
            int r = idx >> 3, c = (idx & 7) * 8;
            cp16(ksb + (r*KPADH + c)*2, Kg + idx*8);
        }
        #pragma unroll
        for (int it = 0; it < 8; it++) {
            int idx = tid + it*128;
            int d = idx >> 4, c = (idx & 15) * 8;
            cp16(vtb + (d*VPADH + c)*2, Vtg + (size_t)d*Nseq + c);
        }
        cp_commit();
    }

    float M0 = -1e30f, M1 = -1e30f, L0 = 0.f, L1 = 0.f;
    float Of[8][4];
    #pragma unroll
    for (int dc = 0; dc < 8; dc++)
        #pragma unroll
        for (int j = 0; j < 4; j++) Of[dc][j] = 0.f;

    for (int kt = 0; kt < 16; kt++) {
        cp_wait0();
        __syncthreads();
        const int buf = kt & 1;

        if (kt < 15) {
            const int nb = buf ^ 1;
            uint32_t ksb = smbase + (nb*BUF_HALVES)*2;
            uint32_t vtb = ksb + KS_HALVES*2;
            const __half* Kt = Kg + (size_t)(kt+1)*128*Dh;
            const __half* Vs = Vtg + (kt+1)*128;
            #pragma unroll
            for (int it = 0; it < 8; it++) {
                int idx = tid + it*128;
                int r = idx >> 3, c = (idx & 7) * 8;
                cp16(ksb + (r*KPADH + c)*2, Kt + idx*8);
            }
            #pragma unroll
            for (int it = 0; it < 8; it++) {
                int idx = tid + it*128;
                int d = idx >> 4, c = (idx & 15) * 8;
                cp16(vtb + (d*VPADH + c)*2, Vs + (size_t)d*Nseq + c);
            }
            cp_commit();
        }

        const uint32_t ks_u32 = smbase + (buf*BUF_HALVES)*2;
        const uint32_t vt_u32 = ks_u32 + KS_HALVES*2;

        uint32_t sd[16][2];
        #pragma unroll
        for (int c = 0; c < 16; c++) {
            const uint32_t rowb = ks_u32 + (uint32_t)(8*c + lrow)*(KPADH*2) + (uint32_t)lhi*16;
            uint32_t kb0[4], kb1[4];
            ldsm4(kb0, rowb);
            ldsm4(kb1, rowb + 64);
            sd[c][0] = 0u; sd[c][1] = 0u;
            mma_h16(sd[c], qa[0][0], qa[0][1], qa[0][2], qa[0][3], kb0[0], kb0[1]);
            mma_h16(sd[c], qa[1][0], qa[1][1], qa[1][2], qa[1][3], kb0[2], kb0[3]);
            mma_h16(sd[c], qa[2][0], qa[2][1], qa[2][2], qa[2][3], kb1[0], kb1[1]);
            mma_h16(sd[c], qa[3][0], qa[3][1], qa[3][2], qa[3][3], kb1[2], kb1[3]);
        }

        __half2 hm0 = u2h(sd[0][0]), hm1 = u2h(sd[0][1]);
        #pragma unroll
        for (int c = 1; c < 16; c++) {
            hm0 = __hmax2(hm0, u2h(sd[c][0]));
            hm1 = __hmax2(hm1, u2h(sd[c][1]));
        }
        float m0 = fmaxf(__low2float(hm0), __high2float(hm0));
        float m1 = fmaxf(__low2float(hm1), __high2float(hm1));
        m0 = fmaxf(m0, __shfl_xor_sync(0xffffffffu, m0, 1));
        m0 = fmaxf(m0, __shfl_xor_sync(0xffffffffu, m0, 2));
        m1 = fmaxf(m1, __shfl_xor_sync(0xffffffffu, m1, 1));
        m1 = fmaxf(m1, __shfl_xor_sync(0xffffffffu, m1, 2));
        float mn0 = fmaxf(M0, m0), mn1 = fmaxf(M1, m1);
        float al0 = ex2f(M0 - mn0), al1 = ex2f(M1 - mn1);
        M0 = mn0; M1 = mn1;

        #pragma unroll
        for (int dc = 0; dc < 8; dc++) {
            Of[dc][0] *= al0; Of[dc][1] *= al0;
            Of[dc][2] *= al1; Of[dc][3] *= al1;
        }

        const __half2 sm0 = __float2half2_rn(mn0);
        const __half2 sm1 = __float2half2_rn(mn1);
        #pragma unroll
        for (int c = 0; c < 16; c++) {
            sd[c][0] = ex2h2(h2u(__hsub2(u2h(sd[c][0]), sm0)));
            sd[c][1] = ex2h2(h2u(__hsub2(u2h(sd[c][1]), sm1)));
        }

        {
            float sA = 0.f, sB = 0.f;
            #pragma unroll
            for (int c = 0; c < 16; c++) {
                float2 f0 = __half22float2(u2h(sd[c][0]));
                float2 f1 = __half22float2(u2h(sd[c][1]));
                sA += f0.x + f0.y;
                sB += f1.x + f1.y;
            }
            sA += __shfl_xor_sync(0xffffffffu, sA, 1);
            sA += __shfl_xor_sync(0xffffffffu, sA, 2);
            sB += __shfl_xor_sync(0xffffffffu, sB, 1);
            sB += __shfl_xor_sync(0xffffffffu, sB, 2);
            L0 = L0*al0 + sA;
            L1 = L1*al1 + sB;
        }

        uint32_t od[8][2];
        #pragma unroll
        for (int dc = 0; dc < 8; dc++) { od[dc][0] = 0u; od[dc][1] = 0u; }
        #pragma unroll
        for (int dc = 0; dc < 8; dc++) {
            const uint32_t rowb = vt_u32 + (uint32_t)(8*dc + lrow)*(VPADH*2) + (uint32_t)lhi*16;
            uint32_t vb[16];
            ldsm4(vb +  0, rowb);
            ldsm4(vb +  4, rowb + 64);
            ldsm4(vb +  8, rowb + 128);
            ldsm4(vb + 12, rowb + 192);
            #pragma unroll
            for (int kc = 0; kc < 8; kc++) {
                mma_h16(od[dc], sd[2*kc][0], sd[2*kc][1],
                        sd[2*kc+1][0], sd[2*kc+1][1], vb[2*kc], vb[2*kc+1]);
            }
        }
        #pragma unroll
        for (int dc = 0; dc < 8; dc++) {
            float2 f0 = __half22float2(u2h(od[dc][0]));
            float2 f1 = __half22float2(u2h(od[dc][1]));
            Of[dc][0] += f0.x; Of[dc][1] += f0.y;
            Of[dc][2] += f1.x; Of[dc][3] += f1.y;
        }
    }

    const float i0 = 1.f / L0, i1 = 1.f / L1;
    const int bb = bh >> 4, h = bh & 15;
    const int r0 = q0 + rA;
    #pragma unroll
    for (int dc = 0; dc < 8; dc++) {
        uint32_t pa0 = h2u(__floats2half2_rn(Of[dc][0]*i0, Of[dc][1]*i0));
        uint32_t pb0 = h2u(__floats2half2_rn(Of[dc][2]*i1, Of[dc][3]*i1));
        *(uint32_t*)&g_ctxh[(size_t)(bb*Nseq + r0)*HID     + h*64 + 8*dc + 2*q] = pa0;
        *(uint32_t*)&g_ctxh[(size_t)(bb*Nseq + r0 + 8)*HID + h*64 + 8*dc + 2*q] = pb0;
    }
}

// ===========================================================================
// Kernel 3: out = GELU(ctx @ Wo + bo), fp16 mma, 3-stage ring.
// REDESIGN: 16 rows/CTA -> grid=512 (3.46 CTA/SM). 8 warps, warp w owns
// n-chunk n8=w (8 cols) x all 16 rows. 4 mma per k-tile per warp.
// ===========================================================================
#define OPAD 72
__global__ __launch_bounds__(256) void out_kernel(
    const float* __restrict__ bo, float* __restrict__ out)
{
    __shared__ __half As[3][16*OPAD];
    __shared__ __half Bs[3][64*OPAD];
    const int m0 = blockIdx.x * 16;
    const int tid = threadIdx.x;
    const int w = tid >> 5, lane = tid & 31;
    const int q = lane & 3, g = lane >> 2;
    const int rA = g;                     // rows g and g+8

    const uint32_t asb = (uint32_t)__cvta_generic_to_shared(&As[0][0]);
    const uint32_t bsb = (uint32_t)__cvta_generic_to_shared(&Bs[0][0]);

    // loaders: A tile 16x64 = 128 uint4 (tid<128); B tile 64x64 = 512 uint4
    const int alr = tid >> 3, alc = (tid & 7) * 8;       // A rows 0..31 (use <16)
    const int blr = tid >> 3, blc = (tid & 7) * 8;       // B rows 0..31, +32

    // prologue: stages 0 and 1
    #pragma unroll
    for (int st = 0; st < 2; st++) {
        if (tid < 128)
            cp16(asb + (st*16*OPAD + alr*OPAD + alc)*2,
                 &g_ctxh[(size_t)(m0 + alr)*HID + st*64 + alc]);
        cp16(bsb + (st*64*OPAD + blr*OPAD + blc)*2,
             &g_woh[(size_t)blr*HID + st*64 + blc]);
        cp16(bsb + (st*64*OPAD + (blr+32)*OPAD + blc)*2,
             &g_woh[(size_t)(blr+32)*HID + st*64 + blc]);
        cp_commit();
    }

    float acc[4] = {0.f, 0.f, 0.f, 0.f};

    for (int kt = 0; kt < 16; kt++) {
        if (kt == 15) cp_wait0(); else cp_wait1();
        __syncthreads();
        const int st = kt % 3;

        if (kt + 2 < 16) {
            const int ns = (kt + 2) % 3;
            if (tid < 128)
                cp16(asb + (ns*16*OPAD + alr*OPAD + alc)*2,
                     &g_ctxh[(size_t)(m0 + alr)*HID + (kt+2)*64 + alc]);
            cp16(bsb + (ns*64*OPAD + blr*OPAD + blc)*2,
                 &g_woh[(size_t)blr*HID + (kt+2)*64 + blc]);
            cp16(bsb + (ns*64*OPAD + (blr+32)*OPAD + blc)*2,
                 &g_woh[(size_t)(blr+32)*HID + (kt+2)*64 + blc]);
            cp_commit();
        }

        uint32_t a[4][4];
        #pragma unroll
        for (int ks = 0; ks < 4; ks++) {
            a[ks][0] = *(uint32_t*)&As[st][rA*OPAD + 16*ks + 2*q];
            a[ks][1] = *(uint32_t*)&As[st][(rA+8)*OPAD + 16*ks + 2*q];
            a[ks][2] = *(uint32_t*)&As[st][rA*OPAD + 16*ks + 8 + 2*q];
            a[ks][3] = *(uint32_t*)&As[st][(rA+8)*OPAD + 16*ks + 8 + 2*q];
        }
        #pragma unroll
        for (int ks = 0; ks < 4; ks++) {
            uint32_t b0 = *(uint32_t*)&Bs[st][(8*w + g)*OPAD + 16*ks + 2*q];
            uint32_t b1 = *(uint32_t*)&Bs[st][(8*w + g)*OPAD + 16*ks + 8 + 2*q];
            mma_f16(acc, a[ks], b0, b1);
        }
    }

    {
        const int col = 8*w + 2*q;
        float bx = bo[col], by = bo[col + 1];
        float v[4];
        v[0] = acc[0] + bx; v[1] = acc[1] + by;
        v[2] = acc[2] + bx; v[3] = acc[3] + by;
        #pragma unroll
        for (int j = 0; j < 4; j++)
            v[j] = 0.5f * v[j] * (1.0f + erff(v[j] * 0.70710678118654752f));
        float2 oa; oa.x = v[0]; oa.y = v[1];
        float2 ob; ob.x = v[2]; ob.y = v[3];
        *(float2*)&out[(size_t)(m0 + rA)*Cdim + col]     = oa;
        *(float2*)&out[(size_t)(m0 + rA + 8)*Cdim + col] = ob;
    }
}

// ===========================================================================
extern "C" void kernel_launch(void* const* d_in, const int* in_sizes, int n_in,
                              void* d_out, int out_size)
{
    const float* X  = (const float*)d_in[0];   // hidden_states [4,2048,64]
    const float* Wq = (const float*)d_in[1];   // qkv_w [64,3072]
    const float* bq = (const float*)d_in[2];   // qkv_b [3072]
    const float* Wo = (const float*)d_in[3];   // out_w [1024,64]
    const float* bo = (const float*)d_in[4];   // out_b [64]
    float* out = (float*)d_out;

    cudaFuncSetAttribute(attn_kernel,
                         cudaFuncAttributeMaxDynamicSharedMemorySize,
                         SM_ATTN_BYTES);

    wconv_all_kernel<<<112, 256>>>(Wq, Wo);
    qkv_kernel<<<dim3(12, 64), 256>>>(X, bq);
    attn_kernel<<<dim3(Nseq/64, Bsz*Hn), 128, SM_ATTN_BYTES>>>();
    out_kernel<<<MTOT/16, 256>>>(bo, out);
}

// round 16
// speedup vs baseline: 1.0319x; 1.0319x over previous
#include <cuda_runtime.h>
#include <cuda_fp16.h>
#include <math.h>
#include <stdint.h>

#define Bsz  4
#define Nseq 2048
#define Cdim 64
#define Hn   16
#define Dh   64
#define HID  1024
#define MTOT (Bsz*Nseq)     // 8192
#define QSC 0.18033688011112042f            /* 0.125 * log2(e) */

// Scratch (device globals)
__device__ __half g_qh[(size_t)Bsz*Hn*Nseq*Dh];   // [bh][n][d], pre-scaled
__device__ __half g_kh[(size_t)Bsz*Hn*Nseq*Dh];   // [bh][n][d]
__device__ __half g_vt[(size_t)Bsz*Hn*Dh*Nseq];   // [bh][d][n]  (V transposed)
__device__ __half g_ctxh[(size_t)MTOT*HID];       // [n][1024] half
__device__ __half g_woh[(size_t)Cdim*HID];        // [n=64][k=1024] (Wo^T, half)
__device__ __half g_wqh[(size_t)(3*HID)*Cdim];    // [n=3072][k=64] (Wq^T, half)

__device__ __forceinline__ float ex2f(float x) {
    float r; asm("ex2.approx.ftz.f32 %0, %1;" : "=f"(r) : "f"(x)); return r;
}
__device__ __forceinline__ uint32_t ex2h2(uint32_t x) {
    uint32_t r; asm("ex2.approx.f16x2 %0, %1;" : "=r"(r) : "r"(x)); return r;
}
__device__ __forceinline__ uint32_t h2u(__half2 h) { return *(uint32_t*)&h; }
__device__ __forceinline__ __half2 u2h(uint32_t u) { return *(__half2*)&u; }

// fp32-accumulator mma (projection kernels)
__device__ __forceinline__ void mma_f16(float d[4], const uint32_t a[4],
                                        uint32_t b0, uint32_t b1) {
    asm volatile("mma.sync.aligned.m16n8k16.row.col.f32.f16.f16.f32 "
        "{%0,%1,%2,%3}, {%4,%5,%6,%7}, {%8,%9}, {%0,%1,%2,%3};"
        : "+f"(d[0]), "+f"(d[1]), "+f"(d[2]), "+f"(d[3])
        : "r"(a[0]), "r"(a[1]), "r"(a[2]), "r"(a[3]), "r"(b0), "r"(b1));
}
// fp16-accumulator mma (attention)
__device__ __forceinline__ void mma_h16(uint32_t d[2],
                                        uint32_t a0, uint32_t a1, uint32_t a2, uint32_t a3,
                                        uint32_t b0, uint32_t b1) {
    asm volatile("mma.sync.aligned.m16n8k16.row.col.f16.f16.f16.f16 "
        "{%0,%1}, {%2,%3,%4,%5}, {%6,%7}, {%0,%1};"
        : "+r"(d[0]), "+r"(d[1])
        : "r"(a0), "r"(a1), "r"(a2), "r"(a3), "r"(b0), "r"(b1));
}
// ldmatrix x4: four 8x8 b16 matrices -> 4 fragment regs
__device__ __forceinline__ void ldsm4(uint32_t r[4], uint32_t addr) {
    asm volatile("ldmatrix.sync.aligned.m8n8.x4.shared.b16 {%0,%1,%2,%3}, [%4];"
        : "=r"(r[0]), "=r"(r[1]), "=r"(r[2]), "=r"(r[3]) : "r"(addr));
}
__device__ __forceinline__ void cp16(uint32_t dst, const void* src) {
    asm volatile("cp.async.cg.shared.global [%0], [%1], 16;" :: "r"(dst), "l"(src));
}
__device__ __forceinline__ void cp_commit() {
    asm volatile("cp.async.commit_group;");
}
__device__ __forceinline__ void cp_wait0() {
    asm volatile("cp.async.wait_group 0;" ::: "memory");
}
__device__ __forceinline__ void cp_wait1() {
    asm volatile("cp.async.wait_group 1;" ::: "memory");
}

// ===========================================================================
// Kernel 0: merged weight conversion (unchanged).
// ===========================================================================
__global__ __launch_bounds__(256) void wconv_all_kernel(
    const float* __restrict__ Wq, const float* __restrict__ Wo)
{
    const int tid = threadIdx.x;
    if (blockIdx.x < 48) {
        __shared__ float T[64][65];
        const int j0 = blockIdx.x * 64;
        #pragma unroll
        for (int it = 0; it < 16; it++) {
            int idx = tid + it*256;
            int k = idx >> 6, n = idx & 63;
            T[k][n] = Wq[(size_t)k*(3*HID) + j0 + n];
        }
        __syncthreads();
        #pragma unroll
        for (int it = 0; it < 2; it++) {
            int idx = tid + it*256;
            int n = idx >> 3, kb = (idx & 7) * 8;
            uint4 o;
            o.x = h2u(__floats2half2_rn(T[kb+0][n], T[kb+1][n]));
            o.y = h2u(__floats2half2_rn(T[kb+2][n], T[kb+3][n]));
            o.z = h2u(__floats2half2_rn(T[kb+4][n], T[kb+5][n]));
            o.w = h2u(__floats2half2_rn(T[kb+6][n], T[kb+7][n]));
            *(uint4*)&g_wqh[(size_t)(j0 + n)*Cdim + kb] = o;
        }
    } else {
        int base = (blockIdx.x - 48) * 1024 + tid * 4;
        int n = base >> 10, k = base & 1023;
        #pragma unroll
        for (int j = 0; j < 4; j++)
            g_woh[base + j] = __float2half_rn(Wo[(size_t)(k + j)*Cdim + n]);
    }
}

// ===========================================================================
// Kernel 1: QKV projection via fp16 mma (unchanged).
// ===========================================================================
#define XPAD 72
#define VTP 136
__global__ __launch_bounds__(256) void qkv_kernel(
    const float* __restrict__ X, const float* __restrict__ bias)
{
    __shared__ __half Xh[128*XPAD];
    __shared__ __half Wh[64*XPAD];
    __shared__ __half VTs[64*VTP];
    const int m0 = blockIdx.y * 128;
    const int jbase = blockIdx.x * 256;
    const int tid = threadIdx.x;
    const int w = tid >> 5, lane = tid & 31;
    const int q = lane & 3, g = lane >> 2;

    #pragma unroll
    for (int it = 0; it < 8; it++) {
        int idx = tid + it*256;
        int r = idx >> 4, c = (idx & 15) * 4;
        float4 v = ((const float4*)(X + (size_t)m0*Cdim))[idx];
        uint2 p;
        p.x = h2u(__floats2half2_rn(v.x, v.y));
        p.y = h2u(__floats2half2_rn(v.z, v.w));
        *(uint2*)&Xh[r*XPAD + c] = p;
    }
    __syncthreads();

    const int rA = 16*w + g;
    uint32_t a[4][4];
    #pragma unroll
    for (int ks = 0; ks < 4; ks++) {
        a[ks][0] = *(uint32_t*)&Xh[rA*XPAD + 16*ks + 2*q];
        a[ks][1] = *(uint32_t*)&Xh[(rA+8)*XPAD + 16*ks + 2*q];
        a[ks][2] = *(uint32_t*)&Xh[rA*XPAD + 16*ks + 8 + 2*q];
        a[ks][3] = *(uint32_t*)&Xh[(rA+8)*XPAD + 16*ks + 8 + 2*q];
    }

    const int three = jbase / HID;
    const int bb = m0 >> 11, n0 = m0 & 2047;
    const int nA = n0 + rA, nB = n0 + rA + 8;

    for (int js = 0; js < 4; js++) {
        const int j0 = jbase + js*64;
        const int h  = (j0 >> 6) & 15;

        #pragma unroll
        for (int it = 0; it < 2; it++) {
            int idx = tid + it*256;
            int n = idx >> 3, kb = (idx & 7) * 8;
            *(uint4*)&Wh[n*XPAD + kb] =
                *(const uint4*)&g_wqh[(size_t)(j0 + n)*Cdim + kb];
        }
        __syncthreads();

        #pragma unroll
        for (int nc = 0; nc < 8; nc++) {
            float d[4] = {0.f, 0.f, 0.f, 0.f};
            #pragma unroll
            for (int ks = 0; ks < 4; ks++) {
                uint32_t b0 = *(uint32_t*)&Wh[(8*nc + g)*XPAD + 16*ks + 2*q];
                uint32_t b1 = *(uint32_t*)&Wh[(8*nc + g)*XPAD + 16*ks + 8 + 2*q];
                mma_f16(d, a[ks], b0, b1);
            }
            const int col = 8*nc + 2*q;
            float bx = bias[j0 + col], by = bias[j0 + col + 1];
            float v0 = d[0] + bx, v1 = d[1] + by;
            float v2 = d[2] + bx, v3 = d[3] + by;
            if (three == 0) {
                v0 *= QSC; v1 *= QSC; v2 *= QSC; v3 *= QSC;
                *(uint32_t*)&g_qh[((size_t)(bb*Hn + h)*Nseq + nA)*Dh + col] =
                    h2u(__floats2half2_rn(v0, v1));
                *(uint32_t*)&g_qh[((size_t)(bb*Hn + h)*Nseq + nB)*Dh + col] =
                    h2u(__floats2half2_rn(v2, v3));
            } else if (three == 1) {
                *(uint32_t*)&g_kh[((size_t)(bb*Hn + h)*Nseq + nA)*Dh + col] =
                    h2u(__floats2half2_rn(v0, v1));
                *(uint32_t*)&g_kh[((size_t)(bb*Hn + h)*Nseq + nB)*Dh + col] =
                    h2u(__floats2half2_rn(v2, v3));
            } else {
                VTs[(col    )*VTP + rA]     = __float2half_rn(v0);
                VTs[(col + 1)*VTP + rA]     = __float2half_rn(v1);
                VTs[(col    )*VTP + rA + 8] = __float2half_rn(v2);
                VTs[(col + 1)*VTP + rA + 8] = __float2half_rn(v3);
            }
        }

        if (three == 2) {
            __syncthreads();
            size_t base = (size_t)(bb*Hn + h)*Dh;
            #pragma unroll
            for (int it = 0; it < 4; it++) {
                int idx = tid + it*256;
                int d = idx >> 4, c = (idx & 15) * 8;
                *(uint4*)&g_vt[(base + d)*Nseq + n0 + c] = *(uint4*)&VTs[d*VTP + c];
            }
        }
        __syncthreads();
    }
}

// ===========================================================================
// Kernel 2: fp16 flash attention. CHANGE: L kept lane-partial through the
// mainloop (alpha is quad-uniform), quad-reduced ONCE at the end — removes
// 4 dependent shuffles per tile from the serial softmax chain.
// ===========================================================================
#define KPADH 72
#define VPADH 136
#define KS_HALVES (128*KPADH)                 // 9216
#define VT_HALVES (64*VPADH)                  // 8704
#define BUF_HALVES (KS_HALVES + VT_HALVES)    // 17920
#define SM_ATTN_BYTES (2*BUF_HALVES*2)        // 71680 B

__global__ __launch_bounds__(128) void attn_kernel()
{
    extern __shared__ __half smh[];
    const uint32_t smbase = (uint32_t)__cvta_generic_to_shared(smh);

    const int tid = threadIdx.x;
    const int w = tid >> 5, lane = tid & 31;
    const int q = lane & 3, gg = lane >> 2;
    const int lrow = lane & 7, lhi = lane >> 3;
    const int bh = blockIdx.y;
    const int q0 = blockIdx.x * 64;

    const __half* Kg  = g_kh + (size_t)bh*Nseq*Dh;
    const __half* Vtg = g_vt + (size_t)bh*Dh*Nseq;

    {
        const __half* Qg = g_qh + ((size_t)bh*Nseq + q0)*Dh;
        #pragma unroll
        for (int it = 0; it < 4; it++) {
            int idx = tid + it*128;
            int r = idx >> 3, c = (idx & 7) * 8;
            *(uint4*)&smh[r*KPADH + c] = ((const uint4*)Qg)[idx];
        }
    }
    __syncthreads();
    const int rA = 16*w + gg;
    uint32_t qa[4][4];
    #pragma unroll
    for (int ks = 0; ks < 4; ks++) {
        qa[ks][0] = *(uint32_t*)&smh[rA*KPADH + 16*ks + 2*q];
        qa[ks][1] = *(uint32_t*)&smh[(rA+8)*KPADH + 16*ks + 2*q];
        qa[ks][2] = *(uint32_t*)&smh[rA*KPADH + 16*ks + 8 + 2*q];
        qa[ks][3] = *(uint32_t*)&smh[(rA+8)*KPADH + 16*ks + 8 + 2*q];
    }
    __syncthreads();

    {
        uint32_t ksb = smbase;
        uint32_t vtb = smbase + KS_HALVES*2;
        #pragma unroll
        for (int it = 0; it < 8; it++) {
            int idx = tid + it*128;
            int r = idx >> 3, c = (idx & 7) * 8;
            cp16(ksb + (r*KPADH + c)*2, Kg + idx*8);
        }
        #pragma unroll
        for (int it = 0; it < 8; it++) {
            int idx = tid + it*128;
            int d = idx >> 4, c = (idx & 15) * 8;
            cp16(vtb + (d*VPADH + c)*2, Vtg + (size_t)d*Nseq + c);
        }
        cp_commit();
    }

    float M0 = -1e30f, M1 = -1e30f, L0 = 0.f, L1 = 0.f;  // L lane-partial
    float Of[8][4];
    #pragma unroll
    for (int dc = 0; dc < 8; dc++)
        #pragma unroll
        for (int j = 0; j < 4; j++) Of[dc][j] = 0.f;

    for (int kt = 0; kt < 16; kt++) {
        cp_wait0();
        __syncthreads();
        const int buf = kt & 1;

        if (kt < 15) {
            const int nb = buf ^ 1;
            uint32_t ksb = smbase + (nb*BUF_HALVES)*2;
            uint32_t vtb = ksb + KS_HALVES*2;
            const __half* Kt = Kg + (size_t)(kt+1)*128*Dh;
            const __half* Vs = Vtg + (kt+1)*128;
            #pragma unroll
            for (int it = 0; it < 8; it++) {
                int idx = tid + it*128;
                int r = idx >> 3, c = (idx & 7) * 8;
                cp16(ksb + (r*KPADH + c)*2, Kt + idx*8);
            }
            #pragma unroll
            for (int it = 0; it < 8; it++) {
                int idx = tid + it*128;
                int d = idx >> 4, c = (idx & 15) * 8;
                cp16(vtb + (d*VPADH + c)*2, Vs + (size_t)d*Nseq + c);
            }
            cp_commit();
        }

        const uint32_t ks_u32 = smbase + (buf*BUF_HALVES)*2;
        const uint32_t vt_u32 = ks_u32 + KS_HALVES*2;

        uint32_t sd[16][2];
        #pragma unroll
        for (int c = 0; c < 16; c++) {
            const uint32_t rowb = ks_u32 + (uint32_t)(8*c + lrow)*(KPADH*2) + (uint32_t)lhi*16;
            uint32_t kb0[4], kb1[4];
            ldsm4(kb0, rowb);
            ldsm4(kb1, rowb + 64);
            sd[c][0] = 0u; sd[c][1] = 0u;
            mma_h16(sd[c], qa[0][0], qa[0][1], qa[0][2], qa[0][3], kb0[0], kb0[1]);
            mma_h16(sd[c], qa[1][0], qa[1][1], qa[1][2], qa[1][3], kb0[2], kb0[3]);
            mma_h16(sd[c], qa[2][0], qa[2][1], qa[2][2], qa[2][3], kb1[0], kb1[1]);
            mma_h16(sd[c], qa[3][0], qa[3][1], qa[3][2], qa[3][3], kb1[2], kb1[3]);
        }

        __half2 hm0 = u2h(sd[0][0]), hm1 = u2h(sd[0][1]);
        #pragma unroll
        for (int c = 1; c < 16; c++) {
            hm0 = __hmax2(hm0, u2h(sd[c][0]));
            hm1 = __hmax2(hm1, u2h(sd[c][1]));
        }
        float m0 = fmaxf(__low2float(hm0), __high2float(hm0));
        float m1 = fmaxf(__low2float(hm1), __high2float(hm1));
        m0 = fmaxf(m0, __shfl_xor_sync(0xffffffffu, m0, 1));
        m0 = fmaxf(m0, __shfl_xor_sync(0xffffffffu, m0, 2));
        m1 = fmaxf(m1, __shfl_xor_sync(0xffffffffu, m1, 1));
        m1 = fmaxf(m1, __shfl_xor_sync(0xffffffffu, m1, 2));
        float mn0 = fmaxf(M0, m0), mn1 = fmaxf(M1, m1);
        float al0 = ex2f(M0 - mn0), al1 = ex2f(M1 - mn1);
        M0 = mn0; M1 = mn1;

        #pragma unroll
        for (int dc = 0; dc < 8; dc++) {
            Of[dc][0] *= al0; Of[dc][1] *= al0;
            Of[dc][2] *= al1; Of[dc][3] *= al1;
        }

        const __half2 sm0 = __float2half2_rn(mn0);
        const __half2 sm1 = __float2half2_rn(mn1);
        #pragma unroll
        for (int c = 0; c < 16; c++) {
            sd[c][0] = ex2h2(h2u(__hsub2(u2h(sd[c][0]), sm0)));
            sd[c][1] = ex2h2(h2u(__hsub2(u2h(sd[c][1]), sm1)));
        }

        // ---- L: lane-partial accumulation only (no shuffles in loop) ----
        {
            float sA = 0.f, sB = 0.f;
            #pragma unroll
            for (int c = 0; c < 16; c++) {
                float2 f0 = __half22float2(u2h(sd[c][0]));
                float2 f1 = __half22float2(u2h(sd[c][1]));
                sA += f0.x + f0.y;
                sB += f1.x + f1.y;
            }
            L0 = L0*al0 + sA;
            L1 = L1*al1 + sB;
        }

        uint32_t od[8][2];
        #pragma unroll
        for (int dc = 0; dc < 8; dc++) { od[dc][0] = 0u; od[dc][1] = 0u; }
        #pragma unroll
        for (int dc = 0; dc < 8; dc++) {
            const uint32_t rowb = vt_u32 + (uint32_t)(8*dc + lrow)*(VPADH*2) + (uint32_t)lhi*16;
            uint32_t vb[16];
            ldsm4(vb +  0, rowb);
            ldsm4(vb +  4, rowb + 64);
            ldsm4(vb +  8, rowb + 128);
            ldsm4(vb + 12, rowb + 192);
            #pragma unroll
            for (int kc = 0; kc < 8; kc++) {
                mma_h16(od[dc], sd[2*kc][0], sd[2*kc][1],
                        sd[2*kc+1][0], sd[2*kc+1][1], vb[2*kc], vb[2*kc+1]);
            }
        }
        #pragma unroll
        for (int dc = 0; dc < 8; dc++) {
            float2 f0 = __half22float2(u2h(od[dc][0]));
            float2 f1 = __half22float2(u2h(od[dc][1]));
            Of[dc][0] += f0.x; Of[dc][1] += f0.y;
            Of[dc][2] += f1.x; Of[dc][3] += f1.y;
        }
    }

    // ---- final quad reduction of lane-partial L ----
    L0 += __shfl_xor_sync(0xffffffffu, L0, 1);
    L0 += __shfl_xor_sync(0xffffffffu, L0, 2);
    L1 += __shfl_xor_sync(0xffffffffu, L1, 1);
    L1 += __shfl_xor_sync(0xffffffffu, L1, 2);

    const float i0 = 1.f / L0, i1 = 1.f / L1;
    const int bb = bh >> 4, h = bh & 15;
    const int r0 = q0 + rA;
    #pragma unroll
    for (int dc = 0; dc < 8; dc++) {
        uint32_t pa0 = h2u(__floats2half2_rn(Of[dc][0]*i0, Of[dc][1]*i0));
        uint32_t pb0 = h2u(__floats2half2_rn(Of[dc][2]*i1, Of[dc][3]*i1));
        *(uint32_t*)&g_ctxh[(size_t)(bb*Nseq + r0)*HID     + h*64 + 8*dc + 2*q] = pa0;
        *(uint32_t*)&g_ctxh[(size_t)(bb*Nseq + r0 + 8)*HID + h*64 + 8*dc + 2*q] = pb0;
    }
}

// ===========================================================================
// Kernel 3: out = GELU(ctx @ Wo + bo) — round-14 exact version
// (32 rows/CTA, grid 256, 3-stage cp.async ring, wait_group 1).
// ===========================================================================
#define OPAD 72
__global__ __launch_bounds__(256) void out_kernel(
    const float* __restrict__ bo, float* __restrict__ out)
{
    __shared__ __half As[3][32*OPAD];
    __shared__ __half Bs[3][64*OPAD];
    const int m0 = blockIdx.x * 32;
    const int tid = threadIdx.x;
    const int w = tid >> 5, lane = tid & 31;
    const int q = lane & 3, g = lane >> 2;
    const int mg = w & 1;
    const int ng = w >> 1;
    const int rA = 16*mg + g;

    const uint32_t asb = (uint32_t)__cvta_generic_to_shared(&As[0][0]);
    const uint32_t bsb = (uint32_t)__cvta_generic_to_shared(&Bs[0][0]);

    const int lr = tid >> 3, lc = (tid & 7) * 8;

    #pragma unroll
    for (int st = 0; st < 2; st++) {
        cp16(asb + (st*32*OPAD + lr*OPAD + lc)*2,
             &g_ctxh[(size_t)(m0 + lr)*HID + st*64 + lc]);
        cp16(bsb + (st*64*OPAD + lr*OPAD + lc)*2,
             &g_woh[(size_t)lr*HID + st*64 + lc]);
        cp16(bsb + (st*64*OPAD + (lr+32)*OPAD + lc)*2,
             &g_woh[(size_t)(lr+32)*HID + st*64 + lc]);
        cp_commit();
    }

    float acc[2][4];
    #pragma unroll
    for (int nc = 0; nc < 2; nc++)
        #pragma unroll
        for (int j = 0; j < 4; j++) acc[nc][j] = 0.f;

    for (int kt = 0; kt < 16; kt++) {
        if (kt == 15) cp_wait0(); else cp_wait1();
        __syncthreads();
        const int st = kt % 3;

        if (kt + 2 < 16) {
            const int ns = (kt + 2) % 3;
            cp16(asb + (ns*32*OPAD + lr*OPAD + lc)*2,
                 &g_ctxh[(size_t)(m0 + lr)*HID + (kt+2)*64 + lc]);
            cp16(bsb + (ns*64*OPAD + lr*OPAD + lc)*2,
                 &g_woh[(size_t)lr*HID + (kt+2)*64 + lc]);
            cp16(bsb + (ns*64*OPAD + (lr+32)*OPAD + lc)*2,
                 &g_woh[(size_t)(lr+32)*HID + (kt+2)*64 + lc]);
            cp_commit();
        }

        uint32_t a[4][4];
        #pragma unroll
        for (int ks = 0; ks < 4; ks++) {
            a[ks][0] = *(uint32_t*)&As[st][rA*OPAD + 16*ks + 2*q];
            a[ks][1] = *(uint32_t*)&As[st][(rA+8)*OPAD + 16*ks + 2*q];
            a[ks][2] = *(uint32_t*)&As[st][rA*OPAD + 16*ks + 8 + 2*q];
            a[ks][3] = *(uint32_t*)&As[st][(rA+8)*OPAD + 16*ks + 8 + 2*q];
        }
        #pragma unroll
        for (int nc = 0; nc < 2; nc++) {
            const int n8 = 2*ng + nc;
            #pragma unroll
            for (int ks = 0; ks < 4; ks++) {
                uint32_t b0 = *(uint32_t*)&Bs[st][(8*n8 + g)*OPAD + 16*ks + 2*q];
                uint32_t b1 = *(uint32_t*)&Bs[st][(8*n8 + g)*OPAD + 16*ks + 8 + 2*q];
                mma_f16(acc[nc], a[ks], b0, b1);
            }
        }
    }

    #pragma unroll
    for (int nc = 0; nc < 2; nc++) {
        const int col = 8*(2*ng + nc) + 2*q;
        float bx = bo[col], by = bo[col + 1];
        float v[4];
        v[0] = acc[nc][0] + bx; v[1] = acc[nc][1] + by;
        v[2] = acc[nc][2] + bx; v[3] = acc[nc][3] + by;
        #pragma unroll
        for (int j = 0; j < 4; j++)
            v[j] = 0.5f * v[j] * (1.0f + erff(v[j] * 0.70710678118654752f));
        float2 oa; oa.x = v[0]; oa.y = v[1];
        float2 ob; ob.x = v[2]; ob.y = v[3];
        *(float2*)&out[(size_t)(m0 + rA)*Cdim + col]     = oa;
        *(float2*)&out[(size_t)(m0 + rA + 8)*Cdim + col] = ob;
    }
}

// ===========================================================================
extern "C" void kernel_launch(void* const* d_in, const int* in_sizes, int n_in,
                              void* d_out, int out_size)
{
    const float* X  = (const float*)d_in[0];   // hidden_states [4,2048,64]
    const float* Wq = (const float*)d_in[1];   // qkv_w [64,3072]
    const float* bq = (const float*)d_in[2];   // qkv_b [3072]
    const float* Wo = (const float*)d_in[3];   // out_w [1024,64]
    const float* bo = (const float*)d_in[4];   // out_b [64]
    float* out = (float*)d_out;

    cudaFuncSetAttribute(attn_kernel,
                         cudaFuncAttributeMaxDynamicSharedMemorySize,
                         SM_ATTN_BYTES);

    wconv_all_kernel<<<112, 256>>>(Wq, Wo);
    qkv_kernel<<<dim3(12, 64), 256>>>(X, bq);
    attn_kernel<<<dim3(Nseq/64, Bsz*Hn), 128, SM_ATTN_BYTES>>>();
    out_kernel<<<MTOT/32, 256>>>(bo, out);
}